// round 11
// baseline (speedup 1.0000x reference)
#include <cuda_runtime.h>
#include <cuda_fp16.h>
#include <cstdint>
#include <cstddef>

// ================= problem =================
// x:(16,128,112,112)f32  weight:(128,128,3,3)  P:(2,128,128,3,3)  bias:(128)
// out:(16,128,112,112) = conv(x, scatter(weight,P) 9x9, pad 4) + bias

#define TAPS 81

// K2 fragment layout: [tap][cichunk(4)][cotile16(8)][kk(2)][lane(32)] uint4
// (2048 uint4 / tap). Lane's uint4 = m16k16 fp16 A-frag regs {a0,a1,a2,a3}:
//   lane=(row&7)*4+((col&7)>>1), reg=(row>>3)+((col>>3)<<1), half=(col&1)
__device__ uint4 g_K2f[TAPS * 4 * 8 * 2 * 32];

// x transposed to f16 NHWC with baked-in halo: [b][h+4 (120)][w+4 (120)][ci 128]
__device__ uint4 g_xT[16 * 120 * 120 * 128 / 8];

__device__ __forceinline__ uint32_t smem_u32(const void* p) {
    uint32_t a;
    asm("{ .reg .u64 t; cvta.to.shared.u64 t, %1; cvt.u32.u64 %0, t; }" : "=r"(a) : "l"(p));
    return a;
}

#define LDSM4(rv, addr)                                                          \
    asm volatile("ldmatrix.sync.aligned.m8n8.x4.shared.b16 {%0,%1,%2,%3}, [%4];" \
        : "=r"((rv)[0]), "=r"((rv)[1]), "=r"((rv)[2]), "=r"((rv)[3]) : "r"(addr))

#define LDSM2(rv, addr)                                                      \
    asm volatile("ldmatrix.sync.aligned.m8n8.x2.shared.b16 {%0,%1}, [%2];"   \
        : "=r"((rv)[0]), "=r"((rv)[1]) : "r"(addr))

#define HMMA(d, a, b0, b1)                                                   \
    asm volatile("mma.sync.aligned.m16n8k16.row.col.f32.f16.f16.f32 "        \
        "{%0,%1,%2,%3}, {%4,%5,%6,%7}, {%8,%9}, {%0,%1,%2,%3};"              \
        : "+f"((d)[0]), "+f"((d)[1]), "+f"((d)[2]), "+f"((d)[3])             \
        : "r"((a)[0]), "r"((a)[1]), "r"((a)[2]), "r"((a)[3]),                \
          "r"(b0), "r"(b1))

#define CP_ASYNC16(sdst, gsrc)                                               \
    asm volatile("cp.async.cg.shared.global [%0], [%1], 16;"                 \
        :: "r"(sdst), "l"(gsrc) : "memory")
#define CP_COMMIT()   asm volatile("cp.async.commit_group;" ::: "memory")
#define CP_WAIT0()    asm volatile("cp.async.wait_group 0;" ::: "memory")

// ============ pre-pass: transpose x -> f16 NHWC, halo zeroed in-place ============
// grid = (b, hp 0..119), 256 threads. Halo rows written as zeros; interior rows
// transposed through smem with w-halo columns zeroed.
__global__ void transpose_xT(const float* __restrict__ x) {
    __shared__ __half s[112 * 130];
    const int b  = blockIdx.x / 120;
    const int hp = blockIdx.x - b * 120;
    const int tid = threadIdx.x;
    __half* xt = (__half*)g_xT + (((size_t)b * 120 + hp) * 120) * 128;

    if (hp < 4 || hp >= 116) {             // full halo row: 120*128 halves
        uint4 z = make_uint4(0, 0, 0, 0);
        for (int u = tid; u < 1920; u += 256) ((uint4*)xt)[u] = z;
        return;
    }
    const int hh = hp - 4;

    const float* xb = x + ((size_t)b * 128) * 12544 + hh * 112;
    for (int u = tid; u < 128 * 112; u += 256) {
        int ci = u / 112, w = u - ci * 112;
        s[w * 130 + ci] = __float2half_rn(xb[(size_t)ci * 12544 + w]);
    }
    // w halo: pixels 0..3 and 116..119 (8 px * 128 ci = 128 uint4)
    {
        uint4 z = make_uint4(0, 0, 0, 0);
        for (int u = tid; u < 128; u += 256) {
            int side = u >> 6, pw = (u >> 4) & 3, seg = u & 15;
            ((uint4*)(xt + (size_t)(side * 116 + pw) * 128))[seg] = z;
        }
    }
    __syncthreads();

    __half* xti = xt + 4 * 128;
    for (int u = tid; u < 112 * 64; u += 256) {
        int w = u >> 6, cp = u & 63;
        __half2 v = make_half2(s[w * 130 + 2 * cp], s[w * 130 + 2 * cp + 1]);
        *(__half2*)(xti + (size_t)w * 128 + 2 * cp) = v;
    }
}

// ================= stage 1: scatter weights -> fragment-layout f16 K2 =================
__global__ void build_K(const float* __restrict__ weight, const float* __restrict__ P) {
    __shared__ float sK[128][81];
    const int co = blockIdx.x;
    const int ci = threadIdx.x;

    #pragma unroll
    for (int i = 0; i < 81; i++) sK[ci][i] = 0.f;

    const float* P0 = P;
    const float* P1 = P + 128 * 128 * 9;

    #pragma unroll
    for (int kh = 0; kh < 3; kh++) {
        #pragma unroll
        for (int kw = 0; kw < 3; kw++) {
            int widx = ((co * 128 + ci) * 3 + kh) * 3 + kw;
            float w  = weight[widx];
            float ph = (float)(kh * 4) + P0[widx];
            float pw = (float)(kw * 4) + P1[widx];
            ph = fminf(fmaxf(ph, 0.f), 8.f);
            pw = fminf(fmaxf(pw, 0.f), 8.f);
            float fh = floorf(ph), fw = floorf(pw);
            float rh = ph - fh,    rw = pw - fw;
            int ih = (int)fh, iw = (int)fw;
            int ih1 = min(ih + 1, 8), iw1 = min(iw + 1, 8);
            sK[ci][ih  * 9 + iw ] += w * (1.f - rh) * (1.f - rw);
            sK[ci][ih1 * 9 + iw ] += w * rh         * (1.f - rw);
            sK[ci][ih  * 9 + iw1] += w * (1.f - rh) * rw;
            sK[ci][ih1 * 9 + iw1] += w * rh         * rw;
        }
    }
    __syncwarp();

    const int c     = ci >> 5;
    const int kk    = (ci >> 4) & 1;
    const int col   = ci & 15;
    const int iglob = co >> 4;
    const int row   = co & 15;
    const int lane  = (row & 7) * 4 + ((col & 7) >> 1);
    const int reg   = (row >> 3) + ((col >> 3) << 1);
    __half* gh = (__half*)g_K2f;
    const size_t slot = ((((size_t)c * 8 + iglob) * 2 + kk) * 32 + lane) * 8 + reg * 2 + (col & 1);
    for (int tap = 0; tap < 81; tap++)
        gh[(size_t)tap * 16384 + slot] = __float2half_rn(sK[ci][tap]);
}

// ================= stage 2: fp16 implicit-GEMM conv =================
// Occ-2 variant of the proven k32 loop:
//   Block (128 thr, occ 2): 64 co x (4 rows x 56 w). 4 warps = 4 rows.
//   Warp tile: 64co x 56px = 4 m-frags x 7 n-frags. K = ci, 4 chunks of 32.
//   A: fragment-layout LDG, register double-buffered (448-cyc chains cover L2).
//   B: single xs buffer staged per chunk via cp.async from f16 NHWC xT;
//      the co-scheduled block hides the stage+wait gap.
#define XS_STRIDE 80
#define SMEM_TOTAL (768 * XS_STRIDE)      // 61440 B -> 2 blocks/SM fit in 228KB

__global__ __launch_bounds__(128, 2)
void dcls_mma(const float* __restrict__ bias, float* __restrict__ out) {
    extern __shared__ char smem[];
    const uint32_t sb = smem_u32(smem);

    const int tid  = threadIdx.x;
    const int lane = tid & 31;
    const int r    = tid >> 5;       // warp = output row 0..3

    const int s  = blockIdx.x;       // 0..1791
    const int h  = s & 1;            // co half
    const int wt = (s >> 1) & 1;
    const int hg = (s >> 2) % 28;
    const int bb = s / 112;
    const int h0 = hg * 4;
    const int w0 = wt * 56;

    const int bnrow = (lane & 7) + ((lane >> 4) << 3);
    const uint32_t b_lane = (uint32_t)(bnrow * XS_STRIDE + ((lane >> 3) & 1) * 16);

    const char* xtb = (const char*)g_xT + ((size_t)bb * 120 * 120) * 256;

    float acc[4][7][4];
    #pragma unroll
    for (int i = 0; i < 4; i++)
        #pragma unroll
        for (int j = 0; j < 7; j++)
            #pragma unroll
            for (int k = 0; k < 4; k++) acc[i][j][k] = 0.f;

    // stage x chunk c (32 ci = 64 B/pixel): 128 thr x 6 px x 4 cp.async16
    #define STAGE(c) do {                                                        \
        _Pragma("unroll")                                                        \
        for (int i_ = 0; i_ < 6; i_++) {                                         \
            int u  = tid + i_ * 128;           /* pixel 0..767 */                \
            int hp = h0 + (u >> 6);                                              \
            int wp = w0 + (u & 63);                                              \
            const char* src = xtb + ((size_t)(hp * 120 + wp) << 8) + (c) * 64;   \
            uint32_t dst = sb + u * XS_STRIDE;                                   \
            CP_ASYNC16(dst,      src);                                           \
            CP_ASYNC16(dst + 16, src + 16);                                      \
            CP_ASYNC16(dst + 32, src + 32);                                      \
            CP_ASYNC16(dst + 48, src + 48);                                      \
        }                                                                        \
        CP_COMMIT();                                                             \
    } while (0)

    for (int c = 0; c < 4; c++) {
        if (c) __syncthreads();      // previous chunk's readers done
        STAGE(c);

        // overlap the cp.async flight with this chunk's first A-frag loads
        const uint4* Ab = g_K2f + ((size_t)c * 16 + h * 8) * 32 + lane;
        uint4 cur[8], nxt[8];
        #pragma unroll
        for (int t = 0; t < 8; t++) cur[t] = Ab[t * 32];

        CP_WAIT0();
        __syncthreads();

        int dh = 0, dw = 0;
        for (int tap = 0; tap < 81; tap++) {
            if (tap < 80) {
                const uint4* An = Ab + (size_t)(tap + 1) * 2048;
                #pragma unroll
                for (int t = 0; t < 8; t++) nxt[t] = An[t * 32];
            }

            const uint32_t bbase = sb + (uint32_t)(((r + dh) * 64 + dw) * XS_STRIDE) + b_lane;

            #pragma unroll
            for (int kk = 0; kk < 2; kk++) {
                #pragma unroll
                for (int j2 = 0; j2 < 3; j2++) {
                    uint32_t b[4];
                    LDSM4(b, bbase + j2 * 1280 + kk * 32);
                    #pragma unroll
                    for (int i = 0; i < 4; i++) {
                        const uint32_t* a = reinterpret_cast<const uint32_t*>(&cur[i * 2 + kk]);
                        HMMA(acc[i][2 * j2],     a, b[0], b[1]);
                        HMMA(acc[i][2 * j2 + 1], a, b[2], b[3]);
                    }
                }
                uint32_t b2[2];
                LDSM2(b2, bbase + 3 * 1280 + kk * 32);
                #pragma unroll
                for (int i = 0; i < 4; i++) {
                    const uint32_t* a = reinterpret_cast<const uint32_t*>(&cur[i * 2 + kk]);
                    HMMA(acc[i][6], a, b2[0], b2[1]);
                }
            }

            if (tap < 80) {
                #pragma unroll
                for (int t = 0; t < 8; t++) cur[t] = nxt[t];
            }
            if (++dw == 9) { dw = 0; dh++; }
        }
    }

    // ================= epilogue: + bias, float2 stores =================
    const int gq = lane >> 2, tq = lane & 3;
    #pragma unroll
    for (int i = 0; i < 4; i++) {
        const int co = h * 64 + i * 16 + gq;
        const float b0 = bias[co];
        const float b1 = bias[co + 8];
        const size_t o0 = ((size_t)(bb * 128 + co) * 112 + (h0 + r)) * 112 + w0;
        const size_t o1 = o0 + (size_t)8 * 12544;
        #pragma unroll
        for (int j = 0; j < 7; j++) {
            const int wcol = j * 8 + tq * 2;
            *(float2*)(out + o0 + wcol) = make_float2(acc[i][j][0] + b0, acc[i][j][1] + b0);
            *(float2*)(out + o1 + wcol) = make_float2(acc[i][j][2] + b1, acc[i][j][3] + b1);
        }
    }
}

// ================= launch =================
extern "C" void kernel_launch(void* const* d_in, const int* in_sizes, int n_in,
                              void* d_out, int out_size) {
    const float* x      = (const float*)d_in[0];
    const float* weight = (const float*)d_in[1];
    const float* P      = (const float*)d_in[2];
    const float* bias   = (const float*)d_in[3];
    float* out = (float*)d_out;

    transpose_xT<<<16 * 120, 256>>>(x);
    build_K<<<128, 128>>>(weight, P);

    cudaFuncSetAttribute(dcls_mma, cudaFuncAttributeMaxDynamicSharedMemorySize, SMEM_TOTAL);
    dcls_mma<<<1792, 128, SMEM_TOTAL>>>(bias, out);
}